// round 13
// baseline (speedup 1.0000x reference)
#include <cuda_runtime.h>
#include <cstdint>

#define B_    32768
#define IN_   512
#define HID_  1024
#define OUT_  2
#define E_    64
#define NIT   10
#define COMB  (IN_ + E_)

// ---------------- scratch ----------------
__device__ float g_h1[(size_t)B_ * HID_];
__device__ float g_h2[(size_t)B_ * HID_];
__device__ float g_enc[(size_t)B_ * E_];
__device__ float g_comb[(size_t)B_ * COMB];

// ---------------- fp32 tiled GEMM (ENCODER: bit-frozen) ----------------
// Single fp32 accumulator per output, fma, k strictly ascending —
// bit-compatible with the CPU reference's per-output chains. DO NOT alter.
template<int BM, int BN, int BK, int TM, int TN, bool RELU>
__global__ __launch_bounds__(256) void gemm_k(
    const float* __restrict__ A, const float* __restrict__ Bm,
    const float* __restrict__ bias, float* __restrict__ C,
    int M, int N, int K)
{
    __shared__ float As[BK][BM];
    __shared__ float Bs[BK][BN];

    const int tid = threadIdx.x;
    const int bn  = blockIdx.x * BN;
    const int bm  = blockIdx.y * BM;
    const int tx  = tid % (BN / TN);
    const int ty  = tid / (BN / TN);

    float acc[TM][TN];
#pragma unroll
    for (int i = 0; i < TM; i++)
#pragma unroll
        for (int j = 0; j < TN; j++) acc[i][j] = 0.f;

    const int aRow = tid / (BK / 4);
    const int aCol = (tid % (BK / 4)) * 4;
    constexpr int B4 = BK * BN / 4;
    const int bRow = tid / (BN / 4);
    const int bCol = (tid % (BN / 4)) * 4;

    for (int k0 = 0; k0 < K; k0 += BK) {
        {
            float4 v = *reinterpret_cast<const float4*>(
                &A[(size_t)(bm + aRow) * K + k0 + aCol]);
            As[aCol + 0][aRow] = v.x;
            As[aCol + 1][aRow] = v.y;
            As[aCol + 2][aRow] = v.z;
            As[aCol + 3][aRow] = v.w;
        }
        if (B4 == 256 || tid < B4) {
            float4 v = *reinterpret_cast<const float4*>(
                &Bm[(size_t)(k0 + bRow) * N + bn + bCol]);
            *reinterpret_cast<float4*>(&Bs[bRow][bCol]) = v;
        }
        __syncthreads();

#pragma unroll
        for (int kk = 0; kk < BK; kk++) {
            float ra[TM], rb[TN];
#pragma unroll
            for (int i = 0; i < TM; i++) ra[i] = As[kk][ty * TM + i];
#pragma unroll
            for (int j = 0; j < TN; j++) rb[j] = Bs[kk][tx * TN + j];
#pragma unroll
            for (int i = 0; i < TM; i++)
#pragma unroll
                for (int j = 0; j < TN; j++)
                    acc[i][j] = fmaf(ra[i], rb[j], acc[i][j]);
        }
        __syncthreads();
    }

#pragma unroll
    for (int i = 0; i < TM; i++) {
        const int row = bm + ty * TM + i;
#pragma unroll
        for (int j = 0; j < TN; j++) {
            float v = acc[i][j] + bias[bn + tx * TN + j];
            if (RELU) v = fmaxf(v, 0.f);
            C[(size_t)row * N + bn + tx * TN + j] = v;
        }
    }
}

// ---------------- 3xTF32 tensor-core GEMM (Q-NET) ----------------
// Splits done ONCE at tile load into DYNAMIC smem; mainloop = LDS + MMA.
__device__ __forceinline__ uint32_t f2tf32(float x) {
    uint32_t u;
    asm("cvt.rna.tf32.f32 %0, %1;" : "=r"(u) : "f"(x));
    return u;
}

__device__ __forceinline__ void mma_tf32(float c[4],
    uint32_t a0, uint32_t a1, uint32_t a2, uint32_t a3,
    uint32_t b0, uint32_t b1)
{
    asm("mma.sync.aligned.m16n8k8.row.col.f32.tf32.tf32.f32 "
        "{%0,%1,%2,%3}, {%4,%5,%6,%7}, {%8,%9}, {%0,%1,%2,%3};"
        : "+f"(c[0]), "+f"(c[1]), "+f"(c[2]), "+f"(c[3])
        : "r"(a0), "r"(a1), "r"(a2), "r"(a3), "r"(b0), "r"(b1));
}

__device__ __forceinline__ void split_tf32(float x, uint32_t& hi, uint32_t& lo) {
    hi = f2tf32(x);
    lo = f2tf32(x - __uint_as_float(hi));   // residual exact; next 11 bits
}

// smem layout constants (uint32 words)
#define ASTR 36
#define BSTR 68
#define ASZ  (128 * ASTR)
#define BSZ  (32 * BSTR)
#define SMEM3X_BYTES ((2 * ASZ + 2 * BSZ) * 4)

// C[M,N] = act(A[M,K] @ W[K,N] + bias), 3-term tf32: hh + hl + lh.
// CTA: 256 thr = 8 warps; tile M=128 (16 rows/warp), N=64, K-step 32.
template<bool RELU>
__global__ __launch_bounds__(256) void gemm_3xtf32_k(
    const float* __restrict__ A, const float* __restrict__ W,
    const float* __restrict__ bias, float* __restrict__ C,
    int M, int N, int K)
{
    extern __shared__ uint32_t dynsmem[];
    uint32_t* AsH = dynsmem;               // [128][ASTR]
    uint32_t* AsL = AsH + ASZ;             // [128][ASTR]
    uint32_t* BsH = AsL + ASZ;             // [32][BSTR]
    uint32_t* BsL = BsH + BSZ;             // [32][BSTR]

    const int tid  = threadIdx.x;
    const int warp = tid >> 5;
    const int lane = tid & 31;
    const int m0   = blockIdx.y * 128;
    const int n0   = blockIdx.x * 64;

    float acc[8][4];
#pragma unroll
    for (int t = 0; t < 8; t++)
#pragma unroll
        for (int j = 0; j < 4; j++) acc[t][j] = 0.f;

    const int ar = tid >> 3;          // 0..31
    const int ac = (tid & 7) * 4;     // 0..28
    const int br = tid >> 4;          // 0..15
    const int bc = (tid & 15) * 4;    // 0..60

    const int arow = (warp << 4) + (lane >> 2);   // row within 128-tile
    const int akl  = lane & 3;
    const int bcol = lane >> 2;                   // 0..7

    for (int k0 = 0; k0 < K; k0 += 32) {
        // A tile: load + split once
#pragma unroll
        for (int it = 0; it < 4; it++) {
            const int rr = it * 32 + ar;
            float4 v = *reinterpret_cast<const float4*>(
                &A[(size_t)(m0 + rr) * K + k0 + ac]);
            uint32_t h, l;
            split_tf32(v.x, h, l); AsH[rr*ASTR + ac+0] = h; AsL[rr*ASTR + ac+0] = l;
            split_tf32(v.y, h, l); AsH[rr*ASTR + ac+1] = h; AsL[rr*ASTR + ac+1] = l;
            split_tf32(v.z, h, l); AsH[rr*ASTR + ac+2] = h; AsL[rr*ASTR + ac+2] = l;
            split_tf32(v.w, h, l); AsH[rr*ASTR + ac+3] = h; AsL[rr*ASTR + ac+3] = l;
        }
        // B tile: load + split once
#pragma unroll
        for (int it = 0; it < 2; it++) {
            const int rr = it * 16 + br;
            float4 v = *reinterpret_cast<const float4*>(
                &W[(size_t)(k0 + rr) * N + n0 + bc]);
            uint32_t h, l;
            split_tf32(v.x, h, l); BsH[rr*BSTR + bc+0] = h; BsL[rr*BSTR + bc+0] = l;
            split_tf32(v.y, h, l); BsH[rr*BSTR + bc+1] = h; BsL[rr*BSTR + bc+1] = l;
            split_tf32(v.z, h, l); BsH[rr*BSTR + bc+2] = h; BsL[rr*BSTR + bc+2] = l;
            split_tf32(v.w, h, l); BsH[rr*BSTR + bc+3] = h; BsL[rr*BSTR + bc+3] = l;
        }
        __syncthreads();

#pragma unroll
        for (int ks = 0; ks < 4; ks++) {
            const int kk = ks * 8;
            uint32_t aH[4], aL[4];
            aH[0] = AsH[(arow    )*ASTR + kk + akl    ];
            aL[0] = AsL[(arow    )*ASTR + kk + akl    ];
            aH[1] = AsH[(arow + 8)*ASTR + kk + akl    ];
            aL[1] = AsL[(arow + 8)*ASTR + kk + akl    ];
            aH[2] = AsH[(arow    )*ASTR + kk + akl + 4];
            aL[2] = AsL[(arow    )*ASTR + kk + akl + 4];
            aH[3] = AsH[(arow + 8)*ASTR + kk + akl + 4];
            aL[3] = AsL[(arow + 8)*ASTR + kk + akl + 4];
#pragma unroll
            for (int t = 0; t < 8; t++) {
                uint32_t bH0 = BsH[(kk + akl    )*BSTR + t * 8 + bcol];
                uint32_t bH1 = BsH[(kk + akl + 4)*BSTR + t * 8 + bcol];
                uint32_t bL0 = BsL[(kk + akl    )*BSTR + t * 8 + bcol];
                uint32_t bL1 = BsL[(kk + akl + 4)*BSTR + t * 8 + bcol];
                mma_tf32(acc[t], aH[0], aH[1], aH[2], aH[3], bH0, bH1);
                mma_tf32(acc[t], aH[0], aH[1], aH[2], aH[3], bL0, bL1);
                mma_tf32(acc[t], aL[0], aL[1], aL[2], aL[3], bH0, bH1);
            }
        }
        __syncthreads();
    }

    const int row = m0 + arow;
#pragma unroll
    for (int t = 0; t < 8; t++) {
        const int col = n0 + t * 8 + 2 * (lane & 3);
        float b0v = bias[col], b1v = bias[col + 1];
        float v0 = acc[t][0] + b0v, v1 = acc[t][1] + b1v;
        float v2 = acc[t][2] + b0v, v3 = acc[t][3] + b1v;
        if (RELU) {
            v0 = fmaxf(v0, 0.f); v1 = fmaxf(v1, 0.f);
            v2 = fmaxf(v2, 0.f); v3 = fmaxf(v3, 0.f);
        }
        C[(size_t)row * N + col]           = v0;
        C[(size_t)row * N + col + 1]       = v1;
        C[(size_t)(row + 8) * N + col]     = v2;
        C[(size_t)(row + 8) * N + col + 1] = v3;
    }
}

// ---------------- copy x into combined buffer ----------------
__global__ void copyx_k(const float* __restrict__ x, float* __restrict__ comb)
{
    size_t idx = (size_t)blockIdx.x * blockDim.x + threadIdx.x;
    const size_t n4 = (size_t)B_ * IN_ / 4;
    if (idx < n4) {
        size_t r = idx / (IN_ / 4);
        size_t c = idx % (IN_ / 4);
        reinterpret_cast<float4*>(comb)[r * (COMB / 4) + c] =
            reinterpret_cast<const float4*>(x)[idx];
    }
}

// ---- signed weight fetch: s_j * w_j (exact; s = +/-1) ----
__device__ __forceinline__ float sgnw(const float* wr, unsigned m0, unsigned m1, int j)
{
    unsigned b = (j < 32) ? ((m0 >> j) & 1u) : ((m1 >> (j - 32)) & 1u);
    float w = wr[j];
    return b ? w : -w;
}

// ---- tie resolver (verified): numpy pairwise-summation tree for n=64 ----
__device__ unsigned tie_sign_np(const float* __restrict__ wr,
                                unsigned m0, unsigned m1)
{
    float A[8] = {0.f,0.f,0.f,0.f,0.f,0.f,0.f,0.f};
    for (int k = 0; k < 8; k++)
#pragma unroll
        for (int l = 0; l < 8; l++) A[l] += sgnw(wr, m0, m1, 8 * k + l);
    float r = ((A[0] + A[1]) + (A[2] + A[3])) + ((A[4] + A[5]) + (A[6] + A[7]));
    return (r > 0.f) ? 1u : 0u;
}

// ---------------- Hopfield retrieval (verified) ----------------
__global__ __launch_bounds__(256) void hopfield_k(
    const float* __restrict__ enc, const float* __restrict__ W,
    float* __restrict__ comb)
{
    __shared__ float sw [64 * 65];
    __shared__ int   swi[64 * 65];
    const int tid = threadIdx.x;
    for (int i = tid; i < 64 * 64; i += 256) {
        int r = i >> 6, c = i & 63;
        float w = W[i];
        sw [r * 65 + c] = w;
        swi[r * 65 + c] = __float2int_rn(w * 100.f);
    }
    __syncthreads();

    const int lane = tid & 31;
    const int warp = tid >> 5;
    const int s = blockIdx.x * 8 + warp;

    const float e0 = enc[(size_t)s * 64 + lane];
    const float e1 = enc[(size_t)s * 64 + 32 + lane];
    unsigned m0 = __ballot_sync(0xffffffffu, e0 > 0.f);
    unsigned m1 = __ballot_sync(0xffffffffu, e1 > 0.f);

    int act0 = 0, act1 = 0;
    const int* r0p = &swi[lane * 65];
    const int* r1p = &swi[(lane + 32) * 65];
#pragma unroll
    for (int j = 0; j < 32; j++) {
        int w0 = r0p[j], w1 = r1p[j];
        if ((m0 >> j) & 1u) { act0 += w0; act1 += w1; }
        else                { act0 -= w0; act1 -= w1; }
    }
#pragma unroll
    for (int j = 0; j < 32; j++) {
        int w0 = r0p[32 + j], w1 = r1p[32 + j];
        if ((m1 >> j) & 1u) { act0 += w0; act1 += w1; }
        else                { act0 -= w0; act1 -= w1; }
    }

    for (int it = 0; it < NIT; it++) {
        unsigned flips = 0u;
#pragma unroll 1
        for (int i = 0; i < 32; i++) {
            int a = __shfl_sync(0xffffffffu, act0, i);
            unsigned nb = (a != 0) ? ((a > 0) ? 1u : 0u)
                                   : tie_sign_np(&sw[i * 65], m0, m1);
            unsigned ob = (m0 >> i) & 1u;
            if (nb != ob) {
                int d = nb ? 2 : -2;
                const int* wr = &swi[i * 65];
                act0 += d * wr[lane];
                act1 += d * wr[lane + 32];
                m0 ^= (1u << i);
                flips = 1u;
            }
        }
#pragma unroll 1
        for (int i = 0; i < 32; i++) {
            int a = __shfl_sync(0xffffffffu, act1, i);
            unsigned nb = (a != 0) ? ((a > 0) ? 1u : 0u)
                                   : tie_sign_np(&sw[(i + 32) * 65], m0, m1);
            unsigned ob = (m1 >> i) & 1u;
            if (nb != ob) {
                int d = nb ? 2 : -2;
                const int* wr = &swi[(i + 32) * 65];
                act0 += d * wr[lane];
                act1 += d * wr[lane + 32];
                m1 ^= (1u << i);
                flips = 1u;
            }
        }
        if (!flips) break;
    }

    float* dst = &comb[(size_t)s * COMB + IN_];
    dst[lane]      = ((m0 >> lane) & 1u) ? 1.f : 0.f;
    dst[lane + 32] = ((m1 >> lane) & 1u) ? 1.f : 0.f;
}

// ---------------- final layer: warp per row ----------------
__global__ __launch_bounds__(256) void out_k(
    const float* __restrict__ H, const float* __restrict__ W3,
    const float* __restrict__ b3, float* __restrict__ out)
{
    __shared__ float sw[HID_ * OUT_];
    for (int i = threadIdx.x; i < HID_ * OUT_; i += 256) sw[i] = W3[i];
    __syncthreads();

    const int warp = threadIdx.x >> 5, lane = threadIdx.x & 31;
    const int row = blockIdx.x * 8 + warp;
    const float* h = &H[(size_t)row * HID_];
    float s0 = 0.f, s1 = 0.f;
#pragma unroll 8
    for (int k = lane; k < HID_; k += 32) {
        float v = h[k];
        s0 = fmaf(v, sw[k * 2 + 0], s0);
        s1 = fmaf(v, sw[k * 2 + 1], s1);
    }
#pragma unroll
    for (int o = 16; o > 0; o >>= 1) {
        s0 += __shfl_xor_sync(0xffffffffu, s0, o);
        s1 += __shfl_xor_sync(0xffffffffu, s1, o);
    }
    if (lane == 0) {
        out[(size_t)row * 2 + 0] = s0 + b3[0];
        out[(size_t)row * 2 + 1] = s1 + b3[1];
    }
}

// ---------------- launch ----------------
extern "C" void kernel_launch(void* const* d_in, const int* in_sizes, int n_in,
                              void* d_out, int out_size)
{
    const float* x    = (const float*)d_in[0];
    const float* e_w1 = (const float*)d_in[1];
    const float* e_b1 = (const float*)d_in[2];
    const float* e_w2 = (const float*)d_in[3];
    const float* e_b2 = (const float*)d_in[4];
    const float* hopw = (const float*)d_in[5];
    const float* n_w1 = (const float*)d_in[6];
    const float* n_b1 = (const float*)d_in[7];
    const float* n_w2 = (const float*)d_in[8];
    const float* n_b2 = (const float*)d_in[9];
    const float* n_w3 = (const float*)d_in[10];
    const float* n_b3 = (const float*)d_in[11];
    float* out = (float*)d_out;

    float *h1, *h2, *enc, *comb;
    cudaGetSymbolAddress((void**)&h1,   g_h1);
    cudaGetSymbolAddress((void**)&h2,   g_h2);
    cudaGetSymbolAddress((void**)&enc,  g_enc);
    cudaGetSymbolAddress((void**)&comb, g_comb);

    // opt-in to >48KB dynamic smem for the 3xTF32 kernels (host attr; not a
    // stream op, graph-capture safe; idempotent)
    cudaFuncSetAttribute(gemm_3xtf32_k<true>,
                         cudaFuncAttributeMaxDynamicSharedMemorySize,
                         SMEM3X_BYTES);

    dim3 gBig(HID_ / 128, B_ / 128);   // (8, 256)
    dim3 gEnc(E_ / 64, B_ / 128);      // (1, 256)
    dim3 gTC (HID_ / 64, B_ / 128);    // (16, 256)

    // encoder: bit-frozen exact fp32 chains
    gemm_k<128,128,8,8,8,true ><<<gBig, 256>>>(x,  e_w1, e_b1, h1,  B_, HID_, IN_);
    gemm_k<128, 64,8,8,4,false><<<gEnc, 256>>>(h1, e_w2, e_b2, enc, B_, E_,  HID_);

    copyx_k<<<(B_ * IN_ / 4 + 255) / 256, 256>>>(x, comb);
    hopfield_k<<<B_ / 8, 256>>>(enc, hopw, comb);

    // Q-net: 3xTF32 tensor cores, splits hoisted to tile load (dynamic smem)
    gemm_3xtf32_k<true><<<gTC, 256, SMEM3X_BYTES>>>(comb, n_w1, n_b1, h2, B_, HID_, COMB);
    gemm_3xtf32_k<true><<<gTC, 256, SMEM3X_BYTES>>>(h2,   n_w2, n_b2, h1, B_, HID_, HID_);
    out_k<<<B_ / 8, 256>>>(h1, n_w3, n_b3, out);
}

// round 14
// speedup vs baseline: 1.3637x; 1.3637x over previous
#include <cuda_runtime.h>
#include <cuda_bf16.h>
#include <cstdint>

#define B_    32768
#define IN_   512
#define HID_  1024
#define OUT_  2
#define E_    64
#define NIT   10
#define COMB  (IN_ + E_)

// ---------------- scratch ----------------
__device__ float g_h1[(size_t)B_ * HID_];
__device__ float g_h2[(size_t)B_ * HID_];
__device__ float g_enc[(size_t)B_ * E_];
__device__ float g_comb[(size_t)B_ * COMB];

// ---------------- fp32 tiled GEMM (ENCODER: bit-frozen) ----------------
// Single fp32 accumulator per output, fma, k strictly ascending —
// bit-compatible with the CPU reference's per-output chains. DO NOT alter.
template<int BM, int BN, int BK, int TM, int TN, bool RELU>
__global__ __launch_bounds__(256) void gemm_k(
    const float* __restrict__ A, const float* __restrict__ Bm,
    const float* __restrict__ bias, float* __restrict__ C,
    int M, int N, int K)
{
    __shared__ float As[BK][BM];
    __shared__ float Bs[BK][BN];

    const int tid = threadIdx.x;
    const int bn  = blockIdx.x * BN;
    const int bm  = blockIdx.y * BM;
    const int tx  = tid % (BN / TN);
    const int ty  = tid / (BN / TN);

    float acc[TM][TN];
#pragma unroll
    for (int i = 0; i < TM; i++)
#pragma unroll
        for (int j = 0; j < TN; j++) acc[i][j] = 0.f;

    const int aRow = tid / (BK / 4);
    const int aCol = (tid % (BK / 4)) * 4;
    constexpr int B4 = BK * BN / 4;
    const int bRow = tid / (BN / 4);
    const int bCol = (tid % (BN / 4)) * 4;

    for (int k0 = 0; k0 < K; k0 += BK) {
        {
            float4 v = *reinterpret_cast<const float4*>(
                &A[(size_t)(bm + aRow) * K + k0 + aCol]);
            As[aCol + 0][aRow] = v.x;
            As[aCol + 1][aRow] = v.y;
            As[aCol + 2][aRow] = v.z;
            As[aCol + 3][aRow] = v.w;
        }
        if (B4 == 256 || tid < B4) {
            float4 v = *reinterpret_cast<const float4*>(
                &Bm[(size_t)(k0 + bRow) * N + bn + bCol]);
            *reinterpret_cast<float4*>(&Bs[bRow][bCol]) = v;
        }
        __syncthreads();

#pragma unroll
        for (int kk = 0; kk < BK; kk++) {
            float ra[TM], rb[TN];
#pragma unroll
            for (int i = 0; i < TM; i++) ra[i] = As[kk][ty * TM + i];
#pragma unroll
            for (int j = 0; j < TN; j++) rb[j] = Bs[kk][tx * TN + j];
#pragma unroll
            for (int i = 0; i < TM; i++)
#pragma unroll
                for (int j = 0; j < TN; j++)
                    acc[i][j] = fmaf(ra[i], rb[j], acc[i][j]);
        }
        __syncthreads();
    }

#pragma unroll
    for (int i = 0; i < TM; i++) {
        const int row = bm + ty * TM + i;
#pragma unroll
        for (int j = 0; j < TN; j++) {
            float v = acc[i][j] + bias[bn + tx * TN + j];
            if (RELU) v = fmaxf(v, 0.f);
            C[(size_t)row * N + bn + tx * TN + j] = v;
        }
    }
}

// ---------------- bf16x3 tensor-core GEMM (Q-NET) ----------------
// x = hi + lo (two bf16); D = hh + hl + lh in fp32 accum via
// mma.m16n8k16.bf16. Dropped ll/resid terms ~2^-16 relative.
__device__ __forceinline__ void mma_bf16(float c[4],
    uint32_t a0, uint32_t a1, uint32_t a2, uint32_t a3,
    uint32_t b0, uint32_t b1)
{
    asm("mma.sync.aligned.m16n8k16.row.col.f32.bf16.bf16.f32 "
        "{%0,%1,%2,%3}, {%4,%5,%6,%7}, {%8,%9}, {%0,%1,%2,%3};"
        : "+f"(c[0]), "+f"(c[1]), "+f"(c[2]), "+f"(c[3])
        : "r"(a0), "r"(a1), "r"(a2), "r"(a3), "r"(b0), "r"(b1));
}

// pack two consecutive-k values into (H, L): low 16 bits = k-even's bf16
__device__ __forceinline__ void pack2_bf16(float x0, float x1,
                                           uint32_t& H, uint32_t& L)
{
    __nv_bfloat16 h0 = __float2bfloat16_rn(x0);
    __nv_bfloat16 l0 = __float2bfloat16_rn(x0 - __bfloat162float(h0));
    __nv_bfloat16 h1 = __float2bfloat16_rn(x1);
    __nv_bfloat16 l1 = __float2bfloat16_rn(x1 - __bfloat162float(h1));
    H = ((uint32_t)__bfloat16_as_ushort(h1) << 16) | __bfloat16_as_ushort(h0);
    L = ((uint32_t)__bfloat16_as_ushort(l1) << 16) | __bfloat16_as_ushort(l0);
}

#define ASTR2 20   // 16 kpairs + pad (20q mod 32 all-distinct -> conflict-free)
#define BSTR2 72   // 64 cols + pad  (72a mod 32 = 8a -> conflict-free)

// C[M,N] = act(A[M,K] @ W[K,N] + bias). CTA: 256 thr = 8 warps;
// tile M=128 (16 rows/warp), N=64, K-step 32 (= 2 x k16).
template<bool RELU>
__global__ __launch_bounds__(256) void gemm_bf16x3_k(
    const float* __restrict__ A, const float* __restrict__ W,
    const float* __restrict__ bias, float* __restrict__ C,
    int M, int N, int K)
{
    __shared__ uint32_t AsH[128 * ASTR2], AsL[128 * ASTR2];  // [row][kpair]
    __shared__ uint32_t BsH[16 * BSTR2],  BsL[16 * BSTR2];   // [kpair][col]

    const int tid  = threadIdx.x;
    const int warp = tid >> 5;
    const int lane = tid & 31;
    const int m0   = blockIdx.y * 128;
    const int n0   = blockIdx.x * 64;

    float acc[8][4];
#pragma unroll
    for (int t = 0; t < 8; t++)
#pragma unroll
        for (int j = 0; j < 4; j++) acc[t][j] = 0.f;

    const int ar  = tid >> 3;          // 0..31 (row in 32-row group)
    const int ac  = (tid & 7) * 4;     // 0..28 (k offset, even)
    const int br2 = tid >> 4;          // 0..15 (kpair row)
    const int bc  = (tid & 15) * 4;    // 0..60 (col)

    const int arow = (warp << 4) + (lane >> 2);   // row within 128-tile
    const int akl  = lane & 3;
    const int bcol = lane >> 2;                   // 0..7

    for (int k0 = 0; k0 < K; k0 += 32) {
        // A tile: load fp32, split+pack pairs once
#pragma unroll
        for (int it = 0; it < 4; it++) {
            const int rr = it * 32 + ar;
            float4 v = *reinterpret_cast<const float4*>(
                &A[(size_t)(m0 + rr) * K + k0 + ac]);
            uint32_t H, L;
            const int p = ac >> 1;             // kpair index (even)
            pack2_bf16(v.x, v.y, H, L);
            AsH[rr * ASTR2 + p] = H;  AsL[rr * ASTR2 + p] = L;
            pack2_bf16(v.z, v.w, H, L);
            AsH[rr * ASTR2 + p + 1] = H;  AsL[rr * ASTR2 + p + 1] = L;
        }
        // B tile: rows 2*br2 (k even) and 2*br2+1 (k odd), pack across k
        {
            float4 v0 = *reinterpret_cast<const float4*>(
                &W[(size_t)(k0 + 2 * br2    ) * N + n0 + bc]);
            float4 v1 = *reinterpret_cast<const float4*>(
                &W[(size_t)(k0 + 2 * br2 + 1) * N + n0 + bc]);
            uint32_t H, L;
            pack2_bf16(v0.x, v1.x, H, L);
            BsH[br2 * BSTR2 + bc + 0] = H;  BsL[br2 * BSTR2 + bc + 0] = L;
            pack2_bf16(v0.y, v1.y, H, L);
            BsH[br2 * BSTR2 + bc + 1] = H;  BsL[br2 * BSTR2 + bc + 1] = L;
            pack2_bf16(v0.z, v1.z, H, L);
            BsH[br2 * BSTR2 + bc + 2] = H;  BsL[br2 * BSTR2 + bc + 2] = L;
            pack2_bf16(v0.w, v1.w, H, L);
            BsH[br2 * BSTR2 + bc + 3] = H;  BsL[br2 * BSTR2 + bc + 3] = L;
        }
        __syncthreads();

#pragma unroll
        for (int s = 0; s < 2; s++) {          // two k16 steps per K-tile
            const int kp = s * 8;
            uint32_t aH[4], aL[4];
            aH[0] = AsH[(arow    ) * ASTR2 + kp + akl    ];
            aH[1] = AsH[(arow + 8) * ASTR2 + kp + akl    ];
            aH[2] = AsH[(arow    ) * ASTR2 + kp + akl + 4];
            aH[3] = AsH[(arow + 8) * ASTR2 + kp + akl + 4];
            aL[0] = AsL[(arow    ) * ASTR2 + kp + akl    ];
            aL[1] = AsL[(arow + 8) * ASTR2 + kp + akl    ];
            aL[2] = AsL[(arow    ) * ASTR2 + kp + akl + 4];
            aL[3] = AsL[(arow + 8) * ASTR2 + kp + akl + 4];
#pragma unroll
            for (int t = 0; t < 8; t++) {
                uint32_t bH0 = BsH[(kp + akl    ) * BSTR2 + t * 8 + bcol];
                uint32_t bH1 = BsH[(kp + akl + 4) * BSTR2 + t * 8 + bcol];
                uint32_t bL0 = BsL[(kp + akl    ) * BSTR2 + t * 8 + bcol];
                uint32_t bL1 = BsL[(kp + akl + 4) * BSTR2 + t * 8 + bcol];
                mma_bf16(acc[t], aH[0], aH[1], aH[2], aH[3], bH0, bH1);  // hh
                mma_bf16(acc[t], aH[0], aH[1], aH[2], aH[3], bL0, bL1);  // hl
                mma_bf16(acc[t], aL[0], aL[1], aL[2], aL[3], bH0, bH1);  // lh
            }
        }
        __syncthreads();
    }

    const int row = m0 + arow;
#pragma unroll
    for (int t = 0; t < 8; t++) {
        const int col = n0 + t * 8 + 2 * (lane & 3);
        float b0v = bias[col], b1v = bias[col + 1];
        float v0 = acc[t][0] + b0v, v1 = acc[t][1] + b1v;
        float v2 = acc[t][2] + b0v, v3 = acc[t][3] + b1v;
        if (RELU) {
            v0 = fmaxf(v0, 0.f); v1 = fmaxf(v1, 0.f);
            v2 = fmaxf(v2, 0.f); v3 = fmaxf(v3, 0.f);
        }
        C[(size_t)row * N + col]           = v0;
        C[(size_t)row * N + col + 1]       = v1;
        C[(size_t)(row + 8) * N + col]     = v2;
        C[(size_t)(row + 8) * N + col + 1] = v3;
    }
}

// ---------------- copy x into combined buffer ----------------
__global__ void copyx_k(const float* __restrict__ x, float* __restrict__ comb)
{
    size_t idx = (size_t)blockIdx.x * blockDim.x + threadIdx.x;
    const size_t n4 = (size_t)B_ * IN_ / 4;
    if (idx < n4) {
        size_t r = idx / (IN_ / 4);
        size_t c = idx % (IN_ / 4);
        reinterpret_cast<float4*>(comb)[r * (COMB / 4) + c] =
            reinterpret_cast<const float4*>(x)[idx];
    }
}

// ---- signed weight fetch: s_j * w_j (exact; s = +/-1) ----
__device__ __forceinline__ float sgnw(const float* wr, unsigned m0, unsigned m1, int j)
{
    unsigned b = (j < 32) ? ((m0 >> j) & 1u) : ((m1 >> (j - 32)) & 1u);
    float w = wr[j];
    return b ? w : -w;
}

// ---- tie resolver (verified): numpy pairwise-summation tree for n=64 ----
__device__ unsigned tie_sign_np(const float* __restrict__ wr,
                                unsigned m0, unsigned m1)
{
    float A[8] = {0.f,0.f,0.f,0.f,0.f,0.f,0.f,0.f};
    for (int k = 0; k < 8; k++)
#pragma unroll
        for (int l = 0; l < 8; l++) A[l] += sgnw(wr, m0, m1, 8 * k + l);
    float r = ((A[0] + A[1]) + (A[2] + A[3])) + ((A[4] + A[5]) + (A[6] + A[7]));
    return (r > 0.f) ? 1u : 0u;
}

// ---------------- Hopfield retrieval (verified) ----------------
__global__ __launch_bounds__(256) void hopfield_k(
    const float* __restrict__ enc, const float* __restrict__ W,
    float* __restrict__ comb)
{
    __shared__ float sw [64 * 65];
    __shared__ int   swi[64 * 65];
    const int tid = threadIdx.x;
    for (int i = tid; i < 64 * 64; i += 256) {
        int r = i >> 6, c = i & 63;
        float w = W[i];
        sw [r * 65 + c] = w;
        swi[r * 65 + c] = __float2int_rn(w * 100.f);
    }
    __syncthreads();

    const int lane = tid & 31;
    const int warp = tid >> 5;
    const int s = blockIdx.x * 8 + warp;

    const float e0 = enc[(size_t)s * 64 + lane];
    const float e1 = enc[(size_t)s * 64 + 32 + lane];
    unsigned m0 = __ballot_sync(0xffffffffu, e0 > 0.f);
    unsigned m1 = __ballot_sync(0xffffffffu, e1 > 0.f);

    int act0 = 0, act1 = 0;
    const int* r0p = &swi[lane * 65];
    const int* r1p = &swi[(lane + 32) * 65];
#pragma unroll
    for (int j = 0; j < 32; j++) {
        int w0 = r0p[j], w1 = r1p[j];
        if ((m0 >> j) & 1u) { act0 += w0; act1 += w1; }
        else                { act0 -= w0; act1 -= w1; }
    }
#pragma unroll
    for (int j = 0; j < 32; j++) {
        int w0 = r0p[32 + j], w1 = r1p[32 + j];
        if ((m1 >> j) & 1u) { act0 += w0; act1 += w1; }
        else                { act0 -= w0; act1 -= w1; }
    }

    for (int it = 0; it < NIT; it++) {
        unsigned flips = 0u;
#pragma unroll 1
        for (int i = 0; i < 32; i++) {
            int a = __shfl_sync(0xffffffffu, act0, i);
            unsigned nb = (a != 0) ? ((a > 0) ? 1u : 0u)
                                   : tie_sign_np(&sw[i * 65], m0, m1);
            unsigned ob = (m0 >> i) & 1u;
            if (nb != ob) {
                int d = nb ? 2 : -2;
                const int* wr = &swi[i * 65];
                act0 += d * wr[lane];
                act1 += d * wr[lane + 32];
                m0 ^= (1u << i);
                flips = 1u;
            }
        }
#pragma unroll 1
        for (int i = 0; i < 32; i++) {
            int a = __shfl_sync(0xffffffffu, act1, i);
            unsigned nb = (a != 0) ? ((a > 0) ? 1u : 0u)
                                   : tie_sign_np(&sw[(i + 32) * 65], m0, m1);
            unsigned ob = (m1 >> i) & 1u;
            if (nb != ob) {
                int d = nb ? 2 : -2;
                const int* wr = &swi[(i + 32) * 65];
                act0 += d * wr[lane];
                act1 += d * wr[lane + 32];
                m1 ^= (1u << i);
                flips = 1u;
            }
        }
        if (!flips) break;
    }

    float* dst = &comb[(size_t)s * COMB + IN_];
    dst[lane]      = ((m0 >> lane) & 1u) ? 1.f : 0.f;
    dst[lane + 32] = ((m1 >> lane) & 1u) ? 1.f : 0.f;
}

// ---------------- final layer: warp per row ----------------
__global__ __launch_bounds__(256) void out_k(
    const float* __restrict__ H, const float* __restrict__ W3,
    const float* __restrict__ b3, float* __restrict__ out)
{
    __shared__ float sw[HID_ * OUT_];
    for (int i = threadIdx.x; i < HID_ * OUT_; i += 256) sw[i] = W3[i];
    __syncthreads();

    const int warp = threadIdx.x >> 5, lane = threadIdx.x & 31;
    const int row = blockIdx.x * 8 + warp;
    const float* h = &H[(size_t)row * HID_];
    float s0 = 0.f, s1 = 0.f;
#pragma unroll 8
    for (int k = lane; k < HID_; k += 32) {
        float v = h[k];
        s0 = fmaf(v, sw[k * 2 + 0], s0);
        s1 = fmaf(v, sw[k * 2 + 1], s1);
    }
#pragma unroll
    for (int o = 16; o > 0; o >>= 1) {
        s0 += __shfl_xor_sync(0xffffffffu, s0, o);
        s1 += __shfl_xor_sync(0xffffffffu, s1, o);
    }
    if (lane == 0) {
        out[(size_t)row * 2 + 0] = s0 + b3[0];
        out[(size_t)row * 2 + 1] = s1 + b3[1];
    }
}

// ---------------- launch ----------------
extern "C" void kernel_launch(void* const* d_in, const int* in_sizes, int n_in,
                              void* d_out, int out_size)
{
    const float* x    = (const float*)d_in[0];
    const float* e_w1 = (const float*)d_in[1];
    const float* e_b1 = (const float*)d_in[2];
    const float* e_w2 = (const float*)d_in[3];
    const float* e_b2 = (const float*)d_in[4];
    const float* hopw = (const float*)d_in[5];
    const float* n_w1 = (const float*)d_in[6];
    const float* n_b1 = (const float*)d_in[7];
    const float* n_w2 = (const float*)d_in[8];
    const float* n_b2 = (const float*)d_in[9];
    const float* n_w3 = (const float*)d_in[10];
    const float* n_b3 = (const float*)d_in[11];
    float* out = (float*)d_out;

    float *h1, *h2, *enc, *comb;
    cudaGetSymbolAddress((void**)&h1,   g_h1);
    cudaGetSymbolAddress((void**)&h2,   g_h2);
    cudaGetSymbolAddress((void**)&enc,  g_enc);
    cudaGetSymbolAddress((void**)&comb, g_comb);

    dim3 gBig(HID_ / 128, B_ / 128);   // (8, 256)
    dim3 gEnc(E_ / 64, B_ / 128);      // (1, 256)
    dim3 gTC (HID_ / 64, B_ / 128);    // (16, 256)

    // encoder: bit-frozen exact fp32 chains
    gemm_k<128,128,8,8,8,true ><<<gBig, 256>>>(x,  e_w1, e_b1, h1,  B_, HID_, IN_);
    gemm_k<128, 64,8,8,4,false><<<gEnc, 256>>>(h1, e_w2, e_b2, enc, B_, E_,  HID_);

    copyx_k<<<(B_ * IN_ / 4 + 255) / 256, 256>>>(x, comb);
    hopfield_k<<<B_ / 8, 256>>>(enc, hopw, comb);

    // Q-net: bf16x3 tensor cores (m16n8k16; half the mma+LDS of 3xTF32)
    gemm_bf16x3_k<true><<<gTC, 256>>>(comb, n_w1, n_b1, h2, B_, HID_, COMB);
    gemm_bf16x3_k<true><<<gTC, 256>>>(h2,   n_w2, n_b2, h1, B_, HID_, HID_);
    out_k<<<B_ / 8, 256>>>(h1, n_w3, n_b3, out);
}

// round 15
// speedup vs baseline: 1.4501x; 1.0633x over previous
#include <cuda_runtime.h>
#include <cuda_bf16.h>
#include <cstdint>

#define B_    32768
#define IN_   512
#define HID_  1024
#define OUT_  2
#define E_    64
#define NIT   10
#define COMB  (IN_ + E_)

// ---------------- scratch ----------------
__device__ float g_h1[(size_t)B_ * HID_];
__device__ float g_h2[(size_t)B_ * HID_];
__device__ float g_enc[(size_t)B_ * E_];
__device__ float g_retr[(size_t)B_ * E_];

// ---------------- fp32 double-buffered GEMM (ENCODER: chain-frozen) --------
// Per-output arithmetic: single fp32 accumulator, fma, k strictly ascending —
// IDENTICAL chain to the verified kernel; only scheduling (prefetch) differs.
template<int BM, int BN, int BK, int TM, int TN, bool RELU>
__global__ __launch_bounds__(256) void gemm_db_k(
    const float* __restrict__ A, const float* __restrict__ Bm,
    const float* __restrict__ bias, float* __restrict__ C,
    int M, int N, int K)
{
    __shared__ float As[2][BK][BM];
    __shared__ float Bs[2][BK][BN];

    const int tid = threadIdx.x;
    const int bn  = blockIdx.x * BN;
    const int bm  = blockIdx.y * BM;
    const int tx  = tid % (BN / TN);
    const int ty  = tid / (BN / TN);

    float acc[TM][TN];
#pragma unroll
    for (int i = 0; i < TM; i++)
#pragma unroll
        for (int j = 0; j < TN; j++) acc[i][j] = 0.f;

    const int aRow = tid / (BK / 4);
    const int aCol = (tid % (BK / 4)) * 4;
    constexpr int B4 = BK * BN / 4;
    const int bRow = tid / (BN / 4);
    const int bCol = (tid % (BN / 4)) * 4;

    const int T = K / BK;

    // preload tile 0
    {
        float4 v = *reinterpret_cast<const float4*>(
            &A[(size_t)(bm + aRow) * K + aCol]);
        As[0][aCol + 0][aRow] = v.x;
        As[0][aCol + 1][aRow] = v.y;
        As[0][aCol + 2][aRow] = v.z;
        As[0][aCol + 3][aRow] = v.w;
        if (B4 == 256 || tid < B4) {
            float4 w = *reinterpret_cast<const float4*>(
                &Bm[(size_t)bRow * N + bn + bCol]);
            *reinterpret_cast<float4*>(&Bs[0][bRow][bCol]) = w;
        }
    }
    __syncthreads();

    for (int t = 0; t < T; t++) {
        float4 rA, rB;
        const bool has = (t + 1 < T);
        if (has) {
            const int k0 = (t + 1) * BK;
            rA = *reinterpret_cast<const float4*>(
                &A[(size_t)(bm + aRow) * K + k0 + aCol]);
            if (B4 == 256 || tid < B4)
                rB = *reinterpret_cast<const float4*>(
                    &Bm[(size_t)(k0 + bRow) * N + bn + bCol]);
        }
        const int buf = t & 1;
#pragma unroll
        for (int kk = 0; kk < BK; kk++) {
            float ra[TM], rb[TN];
#pragma unroll
            for (int i = 0; i < TM; i++) ra[i] = As[buf][kk][ty * TM + i];
#pragma unroll
            for (int j = 0; j < TN; j++) rb[j] = Bs[buf][kk][tx * TN + j];
#pragma unroll
            for (int i = 0; i < TM; i++)
#pragma unroll
                for (int j = 0; j < TN; j++)
                    acc[i][j] = fmaf(ra[i], rb[j], acc[i][j]);
        }
        if (has) {
            const int nb = (t + 1) & 1;
            As[nb][aCol + 0][aRow] = rA.x;
            As[nb][aCol + 1][aRow] = rA.y;
            As[nb][aCol + 2][aRow] = rA.z;
            As[nb][aCol + 3][aRow] = rA.w;
            if (B4 == 256 || tid < B4)
                *reinterpret_cast<float4*>(&Bs[nb][bRow][bCol]) = rB;
        }
        __syncthreads();
    }

#pragma unroll
    for (int i = 0; i < TM; i++) {
        const int row = bm + ty * TM + i;
#pragma unroll
        for (int j = 0; j < TN; j++) {
            float v = acc[i][j] + bias[bn + tx * TN + j];
            if (RELU) v = fmaxf(v, 0.f);
            C[(size_t)row * N + bn + tx * TN + j] = v;
        }
    }
}

// ---------------- bf16x3 double-buffered tensor-core GEMM (Q-NET) ----------
__device__ __forceinline__ void mma_bf16(float c[4],
    uint32_t a0, uint32_t a1, uint32_t a2, uint32_t a3,
    uint32_t b0, uint32_t b1)
{
    asm("mma.sync.aligned.m16n8k16.row.col.f32.bf16.bf16.f32 "
        "{%0,%1,%2,%3}, {%4,%5,%6,%7}, {%8,%9}, {%0,%1,%2,%3};"
        : "+f"(c[0]), "+f"(c[1]), "+f"(c[2]), "+f"(c[3])
        : "r"(a0), "r"(a1), "r"(a2), "r"(a3), "r"(b0), "r"(b1));
}

__device__ __forceinline__ void pack2_bf16(float x0, float x1,
                                           uint32_t& H, uint32_t& L)
{
    __nv_bfloat16 h0 = __float2bfloat16_rn(x0);
    __nv_bfloat16 l0 = __float2bfloat16_rn(x0 - __bfloat162float(h0));
    __nv_bfloat16 h1 = __float2bfloat16_rn(x1);
    __nv_bfloat16 l1 = __float2bfloat16_rn(x1 - __bfloat162float(h1));
    H = ((uint32_t)__bfloat16_as_ushort(h1) << 16) | __bfloat16_as_ushort(h0);
    L = ((uint32_t)__bfloat16_as_ushort(l1) << 16) | __bfloat16_as_ushort(l0);
}

#define ASTR2 20
#define BSTR2 72
#define AH_OFF 0
#define AL_OFF (128 * ASTR2)
#define BH_OFF (2 * 128 * ASTR2)
#define BL_OFF (2 * 128 * ASTR2 + 16 * BSTR2)
#define STAGE_WORDS (2 * 128 * ASTR2 + 2 * 16 * BSTR2)   // 7424
#define SMEMDB_BYTES (2 * STAGE_WORDS * 4)               // 59392

// C[M,N] = act(A @ W + bias); A is split by column: cols < ksplit from
// A0 (stride lda0), cols >= ksplit from A1 (stride lda1). ksplit % 32 == 0.
template<bool RELU>
__global__ __launch_bounds__(256) void gemm_bf16x3_db_k(
    const float* __restrict__ A0, int lda0,
    const float* __restrict__ A1, int lda1, int ksplit,
    const float* __restrict__ W,
    const float* __restrict__ bias, float* __restrict__ C,
    int M, int N, int K)
{
    extern __shared__ uint32_t dyn[];

    const int tid  = threadIdx.x;
    const int warp = tid >> 5;
    const int lane = tid & 31;
    const int m0   = blockIdx.y * 128;
    const int n0   = blockIdx.x * 64;

    float acc[8][4];
#pragma unroll
    for (int t = 0; t < 8; t++)
#pragma unroll
        for (int j = 0; j < 4; j++) acc[t][j] = 0.f;

    const int ar  = tid >> 3;          // 0..31
    const int ac  = (tid & 7) * 4;     // 0..28
    const int br2 = tid >> 4;          // 0..15
    const int bc  = (tid & 15) * 4;    // 0..60

    const int arow = (warp << 4) + (lane >> 2);
    const int akl  = lane & 3;
    const int bcol = lane >> 2;

    const int T = K / 32;

    // ---- helpers as lambdas ----
    auto loadA = [&](int k0, float4 va[4]) {
        const float* src; int ld, kl;
        if (k0 < ksplit) { src = A0; ld = lda0; kl = k0; }
        else             { src = A1; ld = lda1; kl = k0 - ksplit; }
#pragma unroll
        for (int it = 0; it < 4; it++) {
            const int rr = it * 32 + ar;
            va[it] = *reinterpret_cast<const float4*>(
                &src[(size_t)(m0 + rr) * ld + kl + ac]);
        }
    };
    auto loadB = [&](int k0, float4& v0, float4& v1) {
        v0 = *reinterpret_cast<const float4*>(
            &W[(size_t)(k0 + 2 * br2    ) * N + n0 + bc]);
        v1 = *reinterpret_cast<const float4*>(
            &W[(size_t)(k0 + 2 * br2 + 1) * N + n0 + bc]);
    };
    auto store = [&](int s, const float4 va[4], const float4& v0, const float4& v1) {
        uint32_t* AsH = dyn + s * STAGE_WORDS + AH_OFF;
        uint32_t* AsL = dyn + s * STAGE_WORDS + AL_OFF;
        uint32_t* BsH = dyn + s * STAGE_WORDS + BH_OFF;
        uint32_t* BsL = dyn + s * STAGE_WORDS + BL_OFF;
        const int p = ac >> 1;
        uint32_t H, L;
#pragma unroll
        for (int it = 0; it < 4; it++) {
            const int rr = it * 32 + ar;
            pack2_bf16(va[it].x, va[it].y, H, L);
            AsH[rr * ASTR2 + p]     = H;  AsL[rr * ASTR2 + p]     = L;
            pack2_bf16(va[it].z, va[it].w, H, L);
            AsH[rr * ASTR2 + p + 1] = H;  AsL[rr * ASTR2 + p + 1] = L;
        }
        pack2_bf16(v0.x, v1.x, H, L);
        BsH[br2 * BSTR2 + bc + 0] = H;  BsL[br2 * BSTR2 + bc + 0] = L;
        pack2_bf16(v0.y, v1.y, H, L);
        BsH[br2 * BSTR2 + bc + 1] = H;  BsL[br2 * BSTR2 + bc + 1] = L;
        pack2_bf16(v0.z, v1.z, H, L);
        BsH[br2 * BSTR2 + bc + 2] = H;  BsL[br2 * BSTR2 + bc + 2] = L;
        pack2_bf16(v0.w, v1.w, H, L);
        BsH[br2 * BSTR2 + bc + 3] = H;  BsL[br2 * BSTR2 + bc + 3] = L;
    };

    // preload tile 0
    {
        float4 va[4], v0, v1;
        loadA(0, va);
        loadB(0, v0, v1);
        store(0, va, v0, v1);
    }
    __syncthreads();

    for (int t = 0; t < T; t++) {
        float4 va[4], v0, v1;
        const bool has = (t + 1 < T);
        if (has) {
            loadA((t + 1) * 32, va);
            loadB((t + 1) * 32, v0, v1);
        }
        const int buf = t & 1;
        const uint32_t* AsH = dyn + buf * STAGE_WORDS + AH_OFF;
        const uint32_t* AsL = dyn + buf * STAGE_WORDS + AL_OFF;
        const uint32_t* BsH = dyn + buf * STAGE_WORDS + BH_OFF;
        const uint32_t* BsL = dyn + buf * STAGE_WORDS + BL_OFF;

#pragma unroll
        for (int s = 0; s < 2; s++) {
            const int kp = s * 8;
            uint32_t aH[4], aL[4];
            aH[0] = AsH[(arow    ) * ASTR2 + kp + akl    ];
            aH[1] = AsH[(arow + 8) * ASTR2 + kp + akl    ];
            aH[2] = AsH[(arow    ) * ASTR2 + kp + akl + 4];
            aH[3] = AsH[(arow + 8) * ASTR2 + kp + akl + 4];
            aL[0] = AsL[(arow    ) * ASTR2 + kp + akl    ];
            aL[1] = AsL[(arow + 8) * ASTR2 + kp + akl    ];
            aL[2] = AsL[(arow    ) * ASTR2 + kp + akl + 4];
            aL[3] = AsL[(arow + 8) * ASTR2 + kp + akl + 4];
#pragma unroll
            for (int tt = 0; tt < 8; tt++) {
                uint32_t bH0 = BsH[(kp + akl    ) * BSTR2 + tt * 8 + bcol];
                uint32_t bH1 = BsH[(kp + akl + 4) * BSTR2 + tt * 8 + bcol];
                uint32_t bL0 = BsL[(kp + akl    ) * BSTR2 + tt * 8 + bcol];
                uint32_t bL1 = BsL[(kp + akl + 4) * BSTR2 + tt * 8 + bcol];
                mma_bf16(acc[tt], aH[0], aH[1], aH[2], aH[3], bH0, bH1);
                mma_bf16(acc[tt], aH[0], aH[1], aH[2], aH[3], bL0, bL1);
                mma_bf16(acc[tt], aL[0], aL[1], aL[2], aL[3], bH0, bH1);
            }
        }
        if (has) store((t + 1) & 1, va, v0, v1);
        __syncthreads();
    }

    const int row = m0 + arow;
#pragma unroll
    for (int t = 0; t < 8; t++) {
        const int col = n0 + t * 8 + 2 * (lane & 3);
        float b0v = bias[col], b1v = bias[col + 1];
        float v0 = acc[t][0] + b0v, v1 = acc[t][1] + b1v;
        float v2 = acc[t][2] + b0v, v3 = acc[t][3] + b1v;
        if (RELU) {
            v0 = fmaxf(v0, 0.f); v1 = fmaxf(v1, 0.f);
            v2 = fmaxf(v2, 0.f); v3 = fmaxf(v3, 0.f);
        }
        C[(size_t)row * N + col]           = v0;
        C[(size_t)row * N + col + 1]       = v1;
        C[(size_t)(row + 8) * N + col]     = v2;
        C[(size_t)(row + 8) * N + col + 1] = v3;
    }
}

// ---- signed weight fetch ----
__device__ __forceinline__ float sgnw(const float* wr, unsigned m0, unsigned m1, int j)
{
    unsigned b = (j < 32) ? ((m0 >> j) & 1u) : ((m1 >> (j - 32)) & 1u);
    float w = wr[j];
    return b ? w : -w;
}

// ---- tie resolver (verified): numpy pairwise tree ----
__device__ unsigned tie_sign_np(const float* __restrict__ wr,
                                unsigned m0, unsigned m1)
{
    float A[8] = {0.f,0.f,0.f,0.f,0.f,0.f,0.f,0.f};
    for (int k = 0; k < 8; k++)
#pragma unroll
        for (int l = 0; l < 8; l++) A[l] += sgnw(wr, m0, m1, 8 * k + l);
    float r = ((A[0] + A[1]) + (A[2] + A[3])) + ((A[4] + A[5]) + (A[6] + A[7]));
    return (r > 0.f) ? 1u : 0u;
}

// ---------------- Hopfield retrieval (verified; writes retr[B,64]) ---------
__global__ __launch_bounds__(256) void hopfield_k(
    const float* __restrict__ enc, const float* __restrict__ W,
    float* __restrict__ retr)
{
    __shared__ float sw [64 * 65];
    __shared__ int   swi[64 * 65];
    const int tid = threadIdx.x;
    for (int i = tid; i < 64 * 64; i += 256) {
        int r = i >> 6, c = i & 63;
        float w = W[i];
        sw [r * 65 + c] = w;
        swi[r * 65 + c] = __float2int_rn(w * 100.f);
    }
    __syncthreads();

    const int lane = tid & 31;
    const int warp = tid >> 5;
    const int s = blockIdx.x * 8 + warp;

    const float e0 = enc[(size_t)s * 64 + lane];
    const float e1 = enc[(size_t)s * 64 + 32 + lane];
    unsigned m0 = __ballot_sync(0xffffffffu, e0 > 0.f);
    unsigned m1 = __ballot_sync(0xffffffffu, e1 > 0.f);

    int act0 = 0, act1 = 0;
    const int* r0p = &swi[lane * 65];
    const int* r1p = &swi[(lane + 32) * 65];
#pragma unroll
    for (int j = 0; j < 32; j++) {
        int w0 = r0p[j], w1 = r1p[j];
        if ((m0 >> j) & 1u) { act0 += w0; act1 += w1; }
        else                { act0 -= w0; act1 -= w1; }
    }
#pragma unroll
    for (int j = 0; j < 32; j++) {
        int w0 = r0p[32 + j], w1 = r1p[32 + j];
        if ((m1 >> j) & 1u) { act0 += w0; act1 += w1; }
        else                { act0 -= w0; act1 -= w1; }
    }

    for (int it = 0; it < NIT; it++) {
        unsigned flips = 0u;
#pragma unroll 1
        for (int i = 0; i < 32; i++) {
            int a = __shfl_sync(0xffffffffu, act0, i);
            unsigned nb = (a != 0) ? ((a > 0) ? 1u : 0u)
                                   : tie_sign_np(&sw[i * 65], m0, m1);
            unsigned ob = (m0 >> i) & 1u;
            if (nb != ob) {
                int d = nb ? 2 : -2;
                const int* wr = &swi[i * 65];
                act0 += d * wr[lane];
                act1 += d * wr[lane + 32];
                m0 ^= (1u << i);
                flips = 1u;
            }
        }
#pragma unroll 1
        for (int i = 0; i < 32; i++) {
            int a = __shfl_sync(0xffffffffu, act1, i);
            unsigned nb = (a != 0) ? ((a > 0) ? 1u : 0u)
                                   : tie_sign_np(&sw[(i + 32) * 65], m0, m1);
            unsigned ob = (m1 >> i) & 1u;
            if (nb != ob) {
                int d = nb ? 2 : -2;
                const int* wr = &swi[(i + 32) * 65];
                act0 += d * wr[lane];
                act1 += d * wr[lane + 32];
                m1 ^= (1u << i);
                flips = 1u;
            }
        }
        if (!flips) break;
    }

    float* dst = &retr[(size_t)s * 64];
    dst[lane]      = ((m0 >> lane) & 1u) ? 1.f : 0.f;
    dst[lane + 32] = ((m1 >> lane) & 1u) ? 1.f : 0.f;
}

// ---------------- final layer: warp per row ----------------
__global__ __launch_bounds__(256) void out_k(
    const float* __restrict__ H, const float* __restrict__ W3,
    const float* __restrict__ b3, float* __restrict__ out)
{
    __shared__ float sw[HID_ * OUT_];
    for (int i = threadIdx.x; i < HID_ * OUT_; i += 256) sw[i] = W3[i];
    __syncthreads();

    const int warp = threadIdx.x >> 5, lane = threadIdx.x & 31;
    const int row = blockIdx.x * 8 + warp;
    const float* h = &H[(size_t)row * HID_];
    float s0 = 0.f, s1 = 0.f;
#pragma unroll 8
    for (int k = lane; k < HID_; k += 32) {
        float v = h[k];
        s0 = fmaf(v, sw[k * 2 + 0], s0);
        s1 = fmaf(v, sw[k * 2 + 1], s1);
    }
#pragma unroll
    for (int o = 16; o > 0; o >>= 1) {
        s0 += __shfl_xor_sync(0xffffffffu, s0, o);
        s1 += __shfl_xor_sync(0xffffffffu, s1, o);
    }
    if (lane == 0) {
        out[(size_t)row * 2 + 0] = s0 + b3[0];
        out[(size_t)row * 2 + 1] = s1 + b3[1];
    }
}

// ---------------- launch ----------------
extern "C" void kernel_launch(void* const* d_in, const int* in_sizes, int n_in,
                              void* d_out, int out_size)
{
    const float* x    = (const float*)d_in[0];
    const float* e_w1 = (const float*)d_in[1];
    const float* e_b1 = (const float*)d_in[2];
    const float* e_w2 = (const float*)d_in[3];
    const float* e_b2 = (const float*)d_in[4];
    const float* hopw = (const float*)d_in[5];
    const float* n_w1 = (const float*)d_in[6];
    const float* n_b1 = (const float*)d_in[7];
    const float* n_w2 = (const float*)d_in[8];
    const float* n_b2 = (const float*)d_in[9];
    const float* n_w3 = (const float*)d_in[10];
    const float* n_b3 = (const float*)d_in[11];
    float* out = (float*)d_out;

    float *h1, *h2, *enc, *retr;
    cudaGetSymbolAddress((void**)&h1,   g_h1);
    cudaGetSymbolAddress((void**)&h2,   g_h2);
    cudaGetSymbolAddress((void**)&enc,  g_enc);
    cudaGetSymbolAddress((void**)&retr, g_retr);

    cudaFuncSetAttribute(gemm_bf16x3_db_k<true>,
                         cudaFuncAttributeMaxDynamicSharedMemorySize,
                         SMEMDB_BYTES);

    dim3 gBig(HID_ / 128, B_ / 128);   // (8, 256)
    dim3 gEnc(E_ / 64, B_ / 128);      // (1, 256)
    dim3 gTC (HID_ / 64, B_ / 128);    // (16, 256)

    // encoder: chain-frozen fp32, double-buffered
    gemm_db_k<128,128,8,8,8,true ><<<gBig, 256>>>(x,  e_w1, e_b1, h1,  B_, HID_, IN_);
    gemm_db_k<128, 64,8,8,4,false><<<gEnc, 256>>>(h1, e_w2, e_b2, enc, B_, E_,  HID_);

    hopfield_k<<<B_ / 8, 256>>>(enc, hopw, retr);

    // Q-net: bf16x3 tensor cores, double-buffered; K4 reads x|retr directly
    gemm_bf16x3_db_k<true><<<gTC, 256, SMEMDB_BYTES>>>(
        x, IN_, retr, E_, IN_, n_w1, n_b1, h2, B_, HID_, COMB);
    gemm_bf16x3_db_k<true><<<gTC, 256, SMEMDB_BYTES>>>(
        h2, HID_, nullptr, 0, HID_ + 32, n_w2, n_b2, h1, B_, HID_, HID_);
    out_k<<<B_ / 8, 256>>>(h1, n_w3, n_b3, out);
}